// round 14
// baseline (speedup 1.0000x reference)
#include <cuda_runtime.h>
#include <cuda_bf16.h>
#include <math.h>
#include <stdint.h>

// Problem constants
#define N_ROWS 8192
#define DIM 128
#define NCLS 100
#define NTI 64                      // 128-row i-blocks
#define NJOBS 2080                  // pairs of 64-col j-blocks (upper tri)

#define M_MARGIN 0.25f
#define NEG_BIG (-1.0e30f)
#define LN2F 0.6931471805599453f
// gamma' = 256 / ln2 (logits computed in base-2 domain)
#define GP2 369.32993046757465f

// Global bf16 rows (normalized features, label-sorted): [N_ROWS][128]
__device__ __nv_bfloat16 g_h[N_ROWS * DIM];
__device__ int g_lab[N_ROWS];           // sorted labels
__device__ int g_perm[N_ROWS];          // new index -> old row
__device__ int g_hist[32 * NCLS];
__device__ unsigned char g_rankArr[N_ROWS];
__device__ unsigned int g_scnt;

// Per-job LSE partials + completion counter
__device__ float g_pm[NJOBS];
__device__ float g_ps[NJOBS];
__device__ float g_nm[NJOBS];
__device__ float g_ns[NJOBS];
__device__ unsigned int g_count;

// smem rows: 128 bf16 = 256B data + 16B pad = 272 B/row
#define SROW_B 272
#define TI_BYTES (128 * SROW_B)     // 34816
#define TJ_BYTES (64 * SROW_B)      // 17408

#define SM_TI   0
#define SM_TJ0  TI_BYTES
#define SM_TJ1  (TI_BYTES + TJ_BYTES)
#define SM_LR   (TI_BYTES + 2 * TJ_BYTES)      // 128 ints
#define SM_LC0  (SM_LR + 512)                  // 64 ints
#define SM_LC1  (SM_LC0 + 256)                 // 64 ints
#define SM_RED  (SM_LC1 + 256)                 // 32 floats
#define SM_FLAG (SM_RED + 128)                 // 4 bytes
#define SMEM_TOTAL (SM_FLAG + 16)              // ~71 KB

// ---------------------------------------------------------------------------
__device__ __forceinline__ float ex2(float x) {
    float r;
    asm("ex2.approx.f32 %0, %1;" : "=f"(r) : "f"(x));
    return r;
}
// base-2 logsumexp merge
__device__ __forceinline__ void lse_merge(float& m, float& s, float m2, float s2) {
    float mx = fmaxf(m, m2);
    s = s * ex2(m - mx) + s2 * ex2(m2 - mx);
    m = mx;
}

// ---------------------------------------------------------------------------
// Kernel 0: deterministic stable counting sort of rows by label.
// 32 blocks x 256. Last block finishes (offsets + scatter).
// ---------------------------------------------------------------------------
__global__ void __launch_bounds__(256)
sort_kernel(const int* __restrict__ labels) {
    __shared__ int sh_lab[256];
    __shared__ int sh_cnt[NCLS];
    __shared__ unsigned char sh_rank[256];
    __shared__ unsigned int sh_flag;
    const int b = blockIdx.x, t = threadIdx.x;
    const int r = b * 256 + t;

    sh_lab[t] = labels[r];
    if (t < NCLS) sh_cnt[t] = 0;
    __syncthreads();
    if (t == 0) {
        #pragma unroll 1
        for (int i = 0; i < 256; ++i) {       // stable in-block ranks
            int c = sh_lab[i];
            int k = sh_cnt[c];
            sh_rank[i] = (unsigned char)k;
            sh_cnt[c] = k + 1;
        }
    }
    __syncthreads();
    g_rankArr[r] = sh_rank[t];
    if (t < NCLS) g_hist[b * NCLS + t] = sh_cnt[t];
    if (t == 0) {
        __threadfence();
        sh_flag = (atomicAdd(&g_scnt, 1u) == 31u) ? 1u : 0u;
    }
    __syncthreads();

    if (sh_flag) {
        __threadfence();
        __shared__ int sh_off[32 * NCLS];
        __shared__ int sh_tot[NCLS];
        __shared__ int sh_start[NCLS];
        for (int i = t; i < 32 * NCLS; i += 256) sh_off[i] = g_hist[i];
        __syncthreads();
        if (t < NCLS) {
            int tot = 0;
            #pragma unroll 1
            for (int bb = 0; bb < 32; ++bb) tot += sh_off[bb * NCLS + t];
            sh_tot[t] = tot;
        }
        __syncthreads();
        if (t == 0) {
            int acc = 0;
            #pragma unroll 1
            for (int c = 0; c < NCLS; ++c) { sh_start[c] = acc; acc += sh_tot[c]; }
        }
        __syncthreads();
        if (t < NCLS) {
            int run = sh_start[t];
            #pragma unroll 1
            for (int bb = 0; bb < 32; ++bb) {
                int v = sh_off[bb * NCLS + t];
                sh_off[bb * NCLS + t] = run;
                run += v;
            }
        }
        __syncthreads();
        #pragma unroll 1
        for (int rr = t; rr < N_ROWS; rr += 256) {
            int c = labels[rr];
            int dst = sh_off[(rr >> 8) * NCLS + c] + (int)g_rankArr[rr];
            g_perm[dst] = rr;
        }
        if (t == 0) g_scnt = 0;   // reset for graph replay
    }
}

// ---------------------------------------------------------------------------
// Kernel 1: L2-normalize PERMUTED rows -> bf16 g_h; write sorted labels.
// ---------------------------------------------------------------------------
__global__ void __launch_bounds__(256)
prep_kernel(const float* __restrict__ feats, const int* __restrict__ labels) {
    int wid = threadIdx.x >> 5;
    int lane = threadIdx.x & 31;
    int r = blockIdx.x * 8 + wid;
    int old = g_perm[r];

    const float4* src = (const float4*)(feats + (size_t)old * DIM);
    float4 v = src[lane];
    float sq = v.x * v.x + v.y * v.y + v.z * v.z + v.w * v.w;
    #pragma unroll
    for (int o = 16; o > 0; o >>= 1) sq += __shfl_xor_sync(0xffffffffu, sq, o);
    float inv = 1.0f / fmaxf(sqrtf(sq), 1e-12f);

    __nv_bfloat162 p0 = __floats2bfloat162_rn(v.x * inv, v.y * inv);
    __nv_bfloat162 p1 = __floats2bfloat162_rn(v.z * inv, v.w * inv);
    uint2 packed = make_uint2(*(uint32_t*)&p0, *(uint32_t*)&p1);
    ((uint2*)(g_h + (size_t)r * DIM))[lane] = packed;
    if (lane == 0) g_lab[r] = labels[old];
}

// ---------------------------------------------------------------------------
// mma / ldmatrix / cp.async wrappers
// ---------------------------------------------------------------------------
__device__ __forceinline__ void ldm_x4(uint32_t& r0, uint32_t& r1,
                                       uint32_t& r2, uint32_t& r3,
                                       uint32_t addr) {
    asm volatile("ldmatrix.sync.aligned.m8n8.x4.shared.b16 {%0,%1,%2,%3}, [%4];"
                 : "=r"(r0), "=r"(r1), "=r"(r2), "=r"(r3) : "r"(addr));
}
__device__ __forceinline__ void mma_16816(float* c, const uint32_t* a,
                                          uint32_t b0, uint32_t b1) {
    asm volatile(
        "mma.sync.aligned.m16n8k16.row.col.f32.bf16.bf16.f32 "
        "{%0,%1,%2,%3}, {%4,%5,%6,%7}, {%8,%9}, {%0,%1,%2,%3};"
        : "+f"(c[0]), "+f"(c[1]), "+f"(c[2]), "+f"(c[3])
        : "r"(a[0]), "r"(a[1]), "r"(a[2]), "r"(a[3]), "r"(b0), "r"(b1));
}
__device__ __forceinline__ void cp16(uint32_t dst, const void* src) {
    asm volatile("cp.async.cg.shared.global [%0], [%1], 16;"
                 :: "r"(dst), "l"(src));
}

// pair-jobs per i-block: 64 - ti; offset(ti) = ti*(129-ti)/2
__device__ __forceinline__ int job_offset(int ti) {
    return (ti * (129 - ti)) >> 1;
}

extern __shared__ char smem_dyn[];

// ---------------------------------------------------------------------------
// Mainloop: 128x64 sim, K=128 bf16, 8 warps (4x2). acc[2][4][4] (32 regs).
// ---------------------------------------------------------------------------
__device__ __forceinline__ void mainloop(
    uint32_t baseI, uint32_t baseJ, int wid, int lane, float acc[2][4][4])
{
    const int wr = wid >> 1;
    const int wc = wid & 1;

    #pragma unroll
    for (int i = 0; i < 2; ++i)
        #pragma unroll
        for (int j = 0; j < 4; ++j)
            #pragma unroll
            for (int k = 0; k < 4; ++k) acc[i][j][k] = 0.0f;

    const int lrow16 = lane & 15;
    const int lhalf  = lane >> 4;

    uint32_t aAddr[2], bAddr[2];
    #pragma unroll
    for (int mf = 0; mf < 2; ++mf)
        aAddr[mf] = baseI + (uint32_t)((wr * 32 + mf * 16 + lrow16) * SROW_B + lhalf * 16);
    #pragma unroll
    for (int nb = 0; nb < 2; ++nb)
        bAddr[nb] = baseJ + (uint32_t)((wc * 32 + nb * 16 + lrow16) * SROW_B + lhalf * 16);

    #pragma unroll
    for (int ks = 0; ks < DIM / 16; ++ks) {      // 8 k-steps
        uint32_t kByte = (uint32_t)(ks * 32);
        uint32_t a[2][4], bb[2][4];
        #pragma unroll
        for (int mf = 0; mf < 2; ++mf)
            ldm_x4(a[mf][0], a[mf][1], a[mf][2], a[mf][3], aAddr[mf] + kByte);
        #pragma unroll
        for (int nb = 0; nb < 2; ++nb)
            ldm_x4(bb[nb][0], bb[nb][1], bb[nb][2], bb[nb][3], bAddr[nb] + kByte);
        #pragma unroll
        for (int mf = 0; mf < 2; ++mf) {
            #pragma unroll
            for (int nb = 0; nb < 2; ++nb) {
                mma_16816(acc[mf][2 * nb + 0], a[mf], bb[nb][0], bb[nb][2]);
                mma_16816(acc[mf][2 * nb + 1], a[mf], bb[nb][1], bb[nb][3]);
            }
        }
    }
}

// ---------------------------------------------------------------------------
// Epilogue: sparse-positive two-pass base-2 LSE.
// EQ=false: provably no positive pairs in this subjob (sorted labels) —
// no label loads, no compare, no branch. EQ=true: rare-branch pos handling.
// ---------------------------------------------------------------------------
template <bool DIAG, bool EQ>
__device__ __forceinline__ void epilogue(
    float acc[2][4][4], const int* lr, const int* lc,
    int ti, int tjh, int wid, int lane,
    float& MP, float& SP, float& MN, float& SN)
{
    const int wr = wid >> 1;
    const int wc = wid & 1;
    const int grp = lane >> 2;
    const int tid4 = lane & 3;

    int lcv[8];
    if (EQ) {
        #pragma unroll
        for (int nf = 0; nf < 4; ++nf)
            #pragma unroll
            for (int cb = 0; cb < 2; ++cb)
                lcv[nf * 2 + cb] = lc[wc * 32 + nf * 8 + tid4 * 2 + cb];
    }

    float mp = NEG_BIG, sp = 0.0f, mn = NEG_BIG;

    // Pass 1: neg logits in-place; eq elements -> pos stream (rare branch)
    #pragma unroll
    for (int mf = 0; mf < 2; ++mf) {
        #pragma unroll
        for (int rh = 0; rh < 2; ++rh) {
            int rloc = wr * 32 + mf * 16 + rh * 8 + grp;
            int li = EQ ? lr[rloc] : 0;
            int gi = ti * 128 + rloc;
            #pragma unroll
            for (int nf = 0; nf < 4; ++nf) {
                #pragma unroll
                for (int cb = 0; cb < 2; ++cb) {
                    float s = acc[mf][nf][rh * 2 + cb];
                    float tn = fmaf(s, GP2, -0.25f * GP2);   // g'(s - 0.25)
                    float un_raw = s + M_MARGIN;
                    float ln = tn * fmaxf(un_raw, 0.0f);
                    if (EQ) {
                        bool eq = (li == lcv[nf * 2 + cb]);
                        if (DIAG) {
                            int cloc = wc * 32 + nf * 8 + tid4 * 2 + cb;
                            bool valid = gi < tjh * 64 + cloc;
                            eq = eq && valid;
                            ln = valid ? ln : -INFINITY;
                        }
                        if (eq) {                            // rare
                            float tp = 0.5f * GP2 - tn;      // g'(0.75 - s)
                            float lp = tp * fmaxf(1.5f - un_raw, 0.0f);
                            float mx = fmaxf(mp, lp);
                            sp = sp * ex2(mp - mx) + ex2(lp - mx);
                            mp = mx;
                            ln = -INFINITY;                  // exclude from neg
                        }
                    }
                    acc[mf][nf][rh * 2 + cb] = ln;
                    mn = fmaxf(mn, ln);
                }
            }
        }
    }

    // Pass 2: unconditional neg accumulate
    float sn = 0.0f;
    #pragma unroll
    for (int mf = 0; mf < 2; ++mf)
        #pragma unroll
        for (int rh = 0; rh < 2; ++rh)
            #pragma unroll
            for (int nf = 0; nf < 4; ++nf)
                #pragma unroll
                for (int cb = 0; cb < 2; ++cb)
                    sn += ex2(acc[mf][nf][rh * 2 + cb] - mn);

    if (EQ) lse_merge(MP, SP, mp, sp);
    lse_merge(MN, SN, mn, sn);
}

// ---------------------------------------------------------------------------
// Kernel 2: pair-job per CTA + fused last-block final reduction.
// ---------------------------------------------------------------------------
__global__ void __launch_bounds__(256, 3)
sim_lse_kernel(float* __restrict__ out) {
    const int bid = blockIdx.x;
    const int t = threadIdx.x;
    const int wid = t >> 5;
    const int lane = t & 31;

    // invert pair-job index: offset(ti) = ti*(129-ti)/2
    int L = bid;
    float disc = 129.0f * 129.0f - 8.0f * (float)L;
    int ti = (int)((129.0f - sqrtf(disc)) * 0.5f);
    if (ti < 0) ti = 0;
    if (ti > NTI - 1) ti = NTI - 1;
    while (ti + 1 <= NTI - 1 && job_offset(ti + 1) <= L) ++ti;
    while (job_offset(ti) > L) --ti;
    const int p = L - job_offset(ti);
    const int tjh0 = 2 * ti + 2 * p;
    const int tjh1 = tjh0 + 1;
    const bool diag = (p == 0);

    char* smem = smem_dyn;
    uint32_t baseI  = (uint32_t)__cvta_generic_to_shared(smem + SM_TI);
    uint32_t baseJ0 = (uint32_t)__cvta_generic_to_shared(smem + SM_TJ0);
    uint32_t baseJ1 = (uint32_t)__cvta_generic_to_shared(smem + SM_TJ1);
    int* lr = (int*)(smem + SM_LR);
    int* lc0 = (int*)(smem + SM_LC0);
    int* lc1 = (int*)(smem + SM_LC1);
    float* red = (float*)(smem + SM_RED);
    unsigned int* flag = (unsigned int*)(smem + SM_FLAG);

    // Load I + J0 + J1 upfront (one async group)
    {
        const char* srcI  = (const char*)(g_h + (size_t)ti * 128 * DIM);
        const char* srcJ0 = (const char*)(g_h + (size_t)tjh0 * 64 * DIM);
        const char* srcJ1 = (const char*)(g_h + (size_t)tjh1 * 64 * DIM);
        #pragma unroll
        for (int it = 0; it < 8; ++it) {
            int idx = t + it * 256;
            int r = idx >> 4, c = idx & 15;
            cp16(baseI + r * SROW_B + c * 16, srcI + idx * 16);
        }
        #pragma unroll
        for (int it = 0; it < 4; ++it) {
            int idx = t + it * 256;
            int r = idx >> 4, c = idx & 15;
            cp16(baseJ0 + r * SROW_B + c * 16, srcJ0 + idx * 16);
        }
        #pragma unroll
        for (int it = 0; it < 4; ++it) {
            int idx = t + it * 256;
            int r = idx >> 4, c = idx & 15;
            cp16(baseJ1 + r * SROW_B + c * 16, srcJ1 + idx * 16);
        }
        asm volatile("cp.async.commit_group;");
    }
    if (t < 128) lr[t] = g_lab[ti * 128 + t];
    if (t < 64)  lc0[t] = g_lab[tjh0 * 64 + t];
    if (t >= 64 && t < 128) lc1[t - 64] = g_lab[tjh1 * 64 + (t - 64)];
    asm volatile("cp.async.wait_group 0;");
    __syncthreads();

    // sorted labels: subjob has positives iff label ranges intersect
    const bool eq0 = diag || (lr[127] == lc0[0]);
    const bool eq1 = diag || (lr[127] == lc1[0]);

    float MP = NEG_BIG, SP = 0.0f, MN = NEG_BIG, SN = 0.0f;
    float acc[2][4][4];

    mainloop(baseI, baseJ0, wid, lane, acc);
    if (diag)     epilogue<true,  true >(acc, lr, lc0, ti, tjh0, wid, lane, MP, SP, MN, SN);
    else if (eq0) epilogue<false, true >(acc, lr, lc0, ti, tjh0, wid, lane, MP, SP, MN, SN);
    else          epilogue<false, false>(acc, lr, lc0, ti, tjh0, wid, lane, MP, SP, MN, SN);

    mainloop(baseI, baseJ1, wid, lane, acc);
    if (diag)     epilogue<true,  true >(acc, lr, lc1, ti, tjh1, wid, lane, MP, SP, MN, SN);
    else if (eq1) epilogue<false, true >(acc, lr, lc1, ti, tjh1, wid, lane, MP, SP, MN, SN);
    else          epilogue<false, false>(acc, lr, lc1, ti, tjh1, wid, lane, MP, SP, MN, SN);

    // Warp reduction
    #pragma unroll
    for (int o = 16; o > 0; o >>= 1) {
        float m2 = __shfl_xor_sync(0xffffffffu, MP, o);
        float s2 = __shfl_xor_sync(0xffffffffu, SP, o);
        lse_merge(MP, SP, m2, s2);
        m2 = __shfl_xor_sync(0xffffffffu, MN, o);
        s2 = __shfl_xor_sync(0xffffffffu, SN, o);
        lse_merge(MN, SN, m2, s2);
    }

    if (lane == 0) {
        red[wid * 4 + 0] = MP; red[wid * 4 + 1] = SP;
        red[wid * 4 + 2] = MN; red[wid * 4 + 3] = SN;
    }
    __syncthreads();
    if (t == 0) {
        float mp = red[0], sp = red[1], mn = red[2], sn = red[3];
        #pragma unroll
        for (int w = 1; w < 8; ++w) {
            lse_merge(mp, sp, red[w * 4 + 0], red[w * 4 + 1]);
            lse_merge(mn, sn, red[w * 4 + 2], red[w * 4 + 3]);
        }
        g_pm[bid] = mp; g_ps[bid] = sp;
        g_nm[bid] = mn; g_ns[bid] = sn;
        __threadfence();
        unsigned int prev = atomicAdd(&g_count, 1u);
        *flag = (prev == NJOBS - 1) ? 1u : 0u;
    }
    __syncthreads();

    // Last CTA: final reduction + softplus
    if (*flag) {
        __threadfence();
        float mp = NEG_BIG, sp = 0.0f;
        float mn = NEG_BIG, sn = 0.0f;
        for (int i = t; i < NJOBS; i += 256) {
            lse_merge(mp, sp, g_pm[i], g_ps[i]);
            lse_merge(mn, sn, g_nm[i], g_ns[i]);
        }
        #pragma unroll
        for (int o = 16; o > 0; o >>= 1) {
            float m2 = __shfl_xor_sync(0xffffffffu, mp, o);
            float s2 = __shfl_xor_sync(0xffffffffu, sp, o);
            lse_merge(mp, sp, m2, s2);
            m2 = __shfl_xor_sync(0xffffffffu, mn, o);
            s2 = __shfl_xor_sync(0xffffffffu, sn, o);
            lse_merge(mn, sn, m2, s2);
        }
        __syncthreads();   // red smem reuse
        if (lane == 0) {
            red[wid * 4 + 0] = mp; red[wid * 4 + 1] = sp;
            red[wid * 4 + 2] = mn; red[wid * 4 + 3] = sn;
        }
        __syncthreads();
        if (t == 0) {
            float MPf = red[0], SPf = red[1], MNf = red[2], SNf = red[3];
            #pragma unroll
            for (int w = 1; w < 8; ++w) {
                lse_merge(MPf, SPf, red[w * 4 + 0], red[w * 4 + 1]);
                lse_merge(MNf, SNf, red[w * 4 + 2], red[w * 4 + 3]);
            }
            // convert base-2 LSEs back to natural log
            float x = LN2F * (MPf + log2f(SPf) + MNf + log2f(SNf));
            out[0] = fmaxf(x, 0.0f) + log1pf(__expf(-fabsf(x)));
            g_count = 0;   // reset for next graph replay
        }
    }
}

// ---------------------------------------------------------------------------
extern "C" void kernel_launch(void* const* d_in, const int* in_sizes, int n_in,
                              void* d_out, int out_size) {
    const float* feats = (const float*)d_in[0];
    const int* labels = (const int*)d_in[1];
    float* out = (float*)d_out;

    cudaFuncSetAttribute(sim_lse_kernel,
                         cudaFuncAttributeMaxDynamicSharedMemorySize, SMEM_TOTAL);

    sort_kernel<<<32, 256>>>(labels);
    prep_kernel<<<N_ROWS / 8, 256>>>(feats, labels);
    sim_lse_kernel<<<NJOBS, 256, SMEM_TOTAL>>>(out);
}

// round 15
// speedup vs baseline: 1.0875x; 1.0875x over previous
#include <cuda_runtime.h>
#include <cuda_bf16.h>
#include <math.h>
#include <stdint.h>

// Problem constants
#define N_ROWS 8192
#define DIM 128
#define NCLS 100
#define NTI 64                      // 128-row i-blocks
#define NJOBS 2080                  // pairs of 64-col j-blocks (upper tri)

#define M_MARGIN 0.25f
#define NEG_BIG (-1.0e30f)
#define LN2F 0.6931471805599453f
// gamma' = 256 / ln2 (logits computed in base-2 domain)
#define GP2 369.32993046757465f

// Global bf16 rows (normalized features, label-sorted): [N_ROWS][128]
__device__ __nv_bfloat16 g_h[N_ROWS * DIM];
__device__ int g_lab[N_ROWS];           // sorted labels
__device__ int g_perm[N_ROWS];          // new index -> old row
__device__ int g_hist[32 * NCLS];
__device__ unsigned char g_rankArr[N_ROWS];
__device__ unsigned int g_scnt;

// Per-job LSE partials + completion counter
__device__ float g_pm[NJOBS];
__device__ float g_ps[NJOBS];
__device__ float g_nm[NJOBS];
__device__ float g_ns[NJOBS];
__device__ unsigned int g_count;

// smem rows: 128 bf16 = 256B data + 16B pad = 272 B/row
#define SROW_B 272
#define TI_BYTES (128 * SROW_B)     // 34816
#define TJ_BYTES (64 * SROW_B)      // 17408

#define SM_TI   0
#define SM_TJ0  TI_BYTES
#define SM_TJ1  (TI_BYTES + TJ_BYTES)
#define SM_LR   (TI_BYTES + 2 * TJ_BYTES)      // 128 ints
#define SM_LC0  (SM_LR + 512)                  // 64 ints
#define SM_LC1  (SM_LC0 + 256)                 // 64 ints
#define SM_RED  (SM_LC1 + 256)                 // 32 floats
#define SM_FLAG (SM_RED + 128)                 // 4 bytes
#define SMEM_TOTAL (SM_FLAG + 16)              // ~71 KB

// ---------------------------------------------------------------------------
__device__ __forceinline__ float ex2(float x) {
    float r;
    asm("ex2.approx.f32 %0, %1;" : "=f"(r) : "f"(x));
    return r;
}
// base-2 logsumexp merge
__device__ __forceinline__ void lse_merge(float& m, float& s, float m2, float s2) {
    float mx = fmaxf(m, m2);
    s = s * ex2(m - mx) + s2 * ex2(m2 - mx);
    m = mx;
}

// ---------------------------------------------------------------------------
// Kernel 0: deterministic stable counting sort of rows by label.
// 32 blocks x 256. Fully parallel rank/count via broadcast scans.
// Last block finishes (offsets + scatter).
// ---------------------------------------------------------------------------
__global__ void __launch_bounds__(256)
sort_kernel(const int* __restrict__ labels) {
    __shared__ int sh_lab[256];
    __shared__ unsigned int sh_flag;
    const int b = blockIdx.x, t = threadIdx.x;
    const int r = b * 256 + t;

    sh_lab[t] = labels[r];
    __syncthreads();

    // stable in-block rank: count of earlier rows with same label
    // (broadcast reads: all threads scan j = 0..255)
    int lab = sh_lab[t];
    int rank = 0;
    #pragma unroll 8
    for (int j = 0; j < 256; ++j)
        rank += (j < t && sh_lab[j] == lab) ? 1 : 0;
    g_rankArr[r] = (unsigned char)rank;

    // per-class block counts (threads 0..NCLS-1, broadcast reads)
    if (t < NCLS) {
        int cnt = 0;
        #pragma unroll 8
        for (int j = 0; j < 256; ++j)
            cnt += (sh_lab[j] == t) ? 1 : 0;
        g_hist[b * NCLS + t] = cnt;
    }
    __syncthreads();
    if (t == 0) {
        __threadfence();
        sh_flag = (atomicAdd(&g_scnt, 1u) == 31u) ? 1u : 0u;
    }
    __syncthreads();

    if (sh_flag) {
        __threadfence();
        __shared__ int sh_off[32 * NCLS];
        __shared__ int sh_tot[NCLS];
        __shared__ int sh_start[NCLS];
        for (int i = t; i < 32 * NCLS; i += 256) sh_off[i] = g_hist[i];
        __syncthreads();
        if (t < NCLS) {
            int tot = 0;
            #pragma unroll 1
            for (int bb = 0; bb < 32; ++bb) tot += sh_off[bb * NCLS + t];
            sh_tot[t] = tot;
        }
        __syncthreads();
        if (t == 0) {
            int acc = 0;
            #pragma unroll 1
            for (int c = 0; c < NCLS; ++c) { sh_start[c] = acc; acc += sh_tot[c]; }
        }
        __syncthreads();
        if (t < NCLS) {
            int run = sh_start[t];
            #pragma unroll 1
            for (int bb = 0; bb < 32; ++bb) {
                int v = sh_off[bb * NCLS + t];
                sh_off[bb * NCLS + t] = run;
                run += v;
            }
        }
        __syncthreads();
        #pragma unroll 1
        for (int rr = t; rr < N_ROWS; rr += 256) {
            int c = labels[rr];
            int dst = sh_off[(rr >> 8) * NCLS + c] + (int)g_rankArr[rr];
            g_perm[dst] = rr;
        }
        if (t == 0) g_scnt = 0;   // reset for graph replay
    }
}

// ---------------------------------------------------------------------------
// Kernel 1: L2-normalize PERMUTED rows -> bf16 g_h; write sorted labels.
// ---------------------------------------------------------------------------
__global__ void __launch_bounds__(256)
prep_kernel(const float* __restrict__ feats, const int* __restrict__ labels) {
    int wid = threadIdx.x >> 5;
    int lane = threadIdx.x & 31;
    int r = blockIdx.x * 8 + wid;
    int old = g_perm[r];

    const float4* src = (const float4*)(feats + (size_t)old * DIM);
    float4 v = src[lane];
    float sq = v.x * v.x + v.y * v.y + v.z * v.z + v.w * v.w;
    #pragma unroll
    for (int o = 16; o > 0; o >>= 1) sq += __shfl_xor_sync(0xffffffffu, sq, o);
    float inv = 1.0f / fmaxf(sqrtf(sq), 1e-12f);

    __nv_bfloat162 p0 = __floats2bfloat162_rn(v.x * inv, v.y * inv);
    __nv_bfloat162 p1 = __floats2bfloat162_rn(v.z * inv, v.w * inv);
    uint2 packed = make_uint2(*(uint32_t*)&p0, *(uint32_t*)&p1);
    ((uint2*)(g_h + (size_t)r * DIM))[lane] = packed;
    if (lane == 0) g_lab[r] = labels[old];
}

// ---------------------------------------------------------------------------
// mma / ldmatrix / cp.async wrappers
// ---------------------------------------------------------------------------
__device__ __forceinline__ void ldm_x4(uint32_t& r0, uint32_t& r1,
                                       uint32_t& r2, uint32_t& r3,
                                       uint32_t addr) {
    asm volatile("ldmatrix.sync.aligned.m8n8.x4.shared.b16 {%0,%1,%2,%3}, [%4];"
                 : "=r"(r0), "=r"(r1), "=r"(r2), "=r"(r3) : "r"(addr));
}
__device__ __forceinline__ void mma_16816(float* c, const uint32_t* a,
                                          uint32_t b0, uint32_t b1) {
    asm volatile(
        "mma.sync.aligned.m16n8k16.row.col.f32.bf16.bf16.f32 "
        "{%0,%1,%2,%3}, {%4,%5,%6,%7}, {%8,%9}, {%0,%1,%2,%3};"
        : "+f"(c[0]), "+f"(c[1]), "+f"(c[2]), "+f"(c[3])
        : "r"(a[0]), "r"(a[1]), "r"(a[2]), "r"(a[3]), "r"(b0), "r"(b1));
}
__device__ __forceinline__ void cp16(uint32_t dst, const void* src) {
    asm volatile("cp.async.cg.shared.global [%0], [%1], 16;"
                 :: "r"(dst), "l"(src));
}

// pair-jobs per i-block: 64 - ti; offset(ti) = ti*(129-ti)/2
__device__ __forceinline__ int job_offset(int ti) {
    return (ti * (129 - ti)) >> 1;
}

extern __shared__ char smem_dyn[];

// ---------------------------------------------------------------------------
// Mainloop: 128x64 sim, K=128 bf16, 8 warps (4x2). acc[2][4][4] (32 regs).
// ---------------------------------------------------------------------------
__device__ __forceinline__ void mainloop(
    uint32_t baseI, uint32_t baseJ, int wid, int lane, float acc[2][4][4])
{
    const int wr = wid >> 1;
    const int wc = wid & 1;

    #pragma unroll
    for (int i = 0; i < 2; ++i)
        #pragma unroll
        for (int j = 0; j < 4; ++j)
            #pragma unroll
            for (int k = 0; k < 4; ++k) acc[i][j][k] = 0.0f;

    const int lrow16 = lane & 15;
    const int lhalf  = lane >> 4;

    uint32_t aAddr[2], bAddr[2];
    #pragma unroll
    for (int mf = 0; mf < 2; ++mf)
        aAddr[mf] = baseI + (uint32_t)((wr * 32 + mf * 16 + lrow16) * SROW_B + lhalf * 16);
    #pragma unroll
    for (int nb = 0; nb < 2; ++nb)
        bAddr[nb] = baseJ + (uint32_t)((wc * 32 + nb * 16 + lrow16) * SROW_B + lhalf * 16);

    #pragma unroll
    for (int ks = 0; ks < DIM / 16; ++ks) {      // 8 k-steps
        uint32_t kByte = (uint32_t)(ks * 32);
        uint32_t a[2][4], bb[2][4];
        #pragma unroll
        for (int mf = 0; mf < 2; ++mf)
            ldm_x4(a[mf][0], a[mf][1], a[mf][2], a[mf][3], aAddr[mf] + kByte);
        #pragma unroll
        for (int nb = 0; nb < 2; ++nb)
            ldm_x4(bb[nb][0], bb[nb][1], bb[nb][2], bb[nb][3], bAddr[nb] + kByte);
        #pragma unroll
        for (int mf = 0; mf < 2; ++mf) {
            #pragma unroll
            for (int nb = 0; nb < 2; ++nb) {
                mma_16816(acc[mf][2 * nb + 0], a[mf], bb[nb][0], bb[nb][2]);
                mma_16816(acc[mf][2 * nb + 1], a[mf], bb[nb][1], bb[nb][3]);
            }
        }
    }
}

// ---------------------------------------------------------------------------
// Epilogue: sparse-positive two-pass base-2 LSE.
// EQ=false: provably no positive pairs in this subjob (sorted labels) —
// no label loads, no compare, no branch. EQ=true: rare-branch pos handling.
// ---------------------------------------------------------------------------
template <bool DIAG, bool EQ>
__device__ __forceinline__ void epilogue(
    float acc[2][4][4], const int* lr, const int* lc,
    int ti, int tjh, int wid, int lane,
    float& MP, float& SP, float& MN, float& SN)
{
    const int wr = wid >> 1;
    const int wc = wid & 1;
    const int grp = lane >> 2;
    const int tid4 = lane & 3;

    int lcv[8];
    if (EQ) {
        #pragma unroll
        for (int nf = 0; nf < 4; ++nf)
            #pragma unroll
            for (int cb = 0; cb < 2; ++cb)
                lcv[nf * 2 + cb] = lc[wc * 32 + nf * 8 + tid4 * 2 + cb];
    }

    float mp = NEG_BIG, sp = 0.0f, mn = NEG_BIG;

    // Pass 1: neg logits in-place; eq elements -> pos stream (rare branch)
    #pragma unroll
    for (int mf = 0; mf < 2; ++mf) {
        #pragma unroll
        for (int rh = 0; rh < 2; ++rh) {
            int rloc = wr * 32 + mf * 16 + rh * 8 + grp;
            int li = EQ ? lr[rloc] : 0;
            int gi = ti * 128 + rloc;
            #pragma unroll
            for (int nf = 0; nf < 4; ++nf) {
                #pragma unroll
                for (int cb = 0; cb < 2; ++cb) {
                    float s = acc[mf][nf][rh * 2 + cb];
                    float tn = fmaf(s, GP2, -0.25f * GP2);   // g'(s - 0.25)
                    float un_raw = s + M_MARGIN;
                    float ln = tn * fmaxf(un_raw, 0.0f);
                    if (EQ) {
                        bool eq = (li == lcv[nf * 2 + cb]);
                        if (DIAG) {
                            int cloc = wc * 32 + nf * 8 + tid4 * 2 + cb;
                            bool valid = gi < tjh * 64 + cloc;
                            eq = eq && valid;
                            ln = valid ? ln : -INFINITY;
                        }
                        if (eq) {                            // rare
                            float tp = 0.5f * GP2 - tn;      // g'(0.75 - s)
                            float lp = tp * fmaxf(1.5f - un_raw, 0.0f);
                            float mx = fmaxf(mp, lp);
                            sp = sp * ex2(mp - mx) + ex2(lp - mx);
                            mp = mx;
                            ln = -INFINITY;                  // exclude from neg
                        }
                    }
                    acc[mf][nf][rh * 2 + cb] = ln;
                    mn = fmaxf(mn, ln);
                }
            }
        }
    }

    // Pass 2: unconditional neg accumulate
    float sn = 0.0f;
    #pragma unroll
    for (int mf = 0; mf < 2; ++mf)
        #pragma unroll
        for (int rh = 0; rh < 2; ++rh)
            #pragma unroll
            for (int nf = 0; nf < 4; ++nf)
                #pragma unroll
                for (int cb = 0; cb < 2; ++cb)
                    sn += ex2(acc[mf][nf][rh * 2 + cb] - mn);

    if (EQ) lse_merge(MP, SP, mp, sp);
    lse_merge(MN, SN, mn, sn);
}

// ---------------------------------------------------------------------------
// Kernel 2: pair-job per CTA + fused last-block final reduction.
// ---------------------------------------------------------------------------
__global__ void __launch_bounds__(256, 3)
sim_lse_kernel(float* __restrict__ out) {
    const int bid = blockIdx.x;
    const int t = threadIdx.x;
    const int wid = t >> 5;
    const int lane = t & 31;

    // invert pair-job index: offset(ti) = ti*(129-ti)/2
    int L = bid;
    float disc = 129.0f * 129.0f - 8.0f * (float)L;
    int ti = (int)((129.0f - sqrtf(disc)) * 0.5f);
    if (ti < 0) ti = 0;
    if (ti > NTI - 1) ti = NTI - 1;
    while (ti + 1 <= NTI - 1 && job_offset(ti + 1) <= L) ++ti;
    while (job_offset(ti) > L) --ti;
    const int p = L - job_offset(ti);
    const int tjh0 = 2 * ti + 2 * p;
    const int tjh1 = tjh0 + 1;
    const bool diag = (p == 0);

    char* smem = smem_dyn;
    uint32_t baseI  = (uint32_t)__cvta_generic_to_shared(smem + SM_TI);
    uint32_t baseJ0 = (uint32_t)__cvta_generic_to_shared(smem + SM_TJ0);
    uint32_t baseJ1 = (uint32_t)__cvta_generic_to_shared(smem + SM_TJ1);
    int* lr = (int*)(smem + SM_LR);
    int* lc0 = (int*)(smem + SM_LC0);
    int* lc1 = (int*)(smem + SM_LC1);
    float* red = (float*)(smem + SM_RED);
    unsigned int* flag = (unsigned int*)(smem + SM_FLAG);

    // Load I + J0 + J1 upfront (one async group)
    {
        const char* srcI  = (const char*)(g_h + (size_t)ti * 128 * DIM);
        const char* srcJ0 = (const char*)(g_h + (size_t)tjh0 * 64 * DIM);
        const char* srcJ1 = (const char*)(g_h + (size_t)tjh1 * 64 * DIM);
        #pragma unroll
        for (int it = 0; it < 8; ++it) {
            int idx = t + it * 256;
            int r = idx >> 4, c = idx & 15;
            cp16(baseI + r * SROW_B + c * 16, srcI + idx * 16);
        }
        #pragma unroll
        for (int it = 0; it < 4; ++it) {
            int idx = t + it * 256;
            int r = idx >> 4, c = idx & 15;
            cp16(baseJ0 + r * SROW_B + c * 16, srcJ0 + idx * 16);
        }
        #pragma unroll
        for (int it = 0; it < 4; ++it) {
            int idx = t + it * 256;
            int r = idx >> 4, c = idx & 15;
            cp16(baseJ1 + r * SROW_B + c * 16, srcJ1 + idx * 16);
        }
        asm volatile("cp.async.commit_group;");
    }
    if (t < 128) lr[t] = g_lab[ti * 128 + t];
    if (t < 64)  lc0[t] = g_lab[tjh0 * 64 + t];
    if (t >= 64 && t < 128) lc1[t - 64] = g_lab[tjh1 * 64 + (t - 64)];
    asm volatile("cp.async.wait_group 0;");
    __syncthreads();

    // sorted labels: subjob has positives iff label ranges intersect
    const bool eq0 = diag || (lr[127] == lc0[0]);
    const bool eq1 = diag || (lr[127] == lc1[0]);

    float MP = NEG_BIG, SP = 0.0f, MN = NEG_BIG, SN = 0.0f;
    float acc[2][4][4];

    mainloop(baseI, baseJ0, wid, lane, acc);
    if (diag)     epilogue<true,  true >(acc, lr, lc0, ti, tjh0, wid, lane, MP, SP, MN, SN);
    else if (eq0) epilogue<false, true >(acc, lr, lc0, ti, tjh0, wid, lane, MP, SP, MN, SN);
    else          epilogue<false, false>(acc, lr, lc0, ti, tjh0, wid, lane, MP, SP, MN, SN);

    mainloop(baseI, baseJ1, wid, lane, acc);
    if (diag)     epilogue<true,  true >(acc, lr, lc1, ti, tjh1, wid, lane, MP, SP, MN, SN);
    else if (eq1) epilogue<false, true >(acc, lr, lc1, ti, tjh1, wid, lane, MP, SP, MN, SN);
    else          epilogue<false, false>(acc, lr, lc1, ti, tjh1, wid, lane, MP, SP, MN, SN);

    // Warp reduction
    #pragma unroll
    for (int o = 16; o > 0; o >>= 1) {
        float m2 = __shfl_xor_sync(0xffffffffu, MP, o);
        float s2 = __shfl_xor_sync(0xffffffffu, SP, o);
        lse_merge(MP, SP, m2, s2);
        m2 = __shfl_xor_sync(0xffffffffu, MN, o);
        s2 = __shfl_xor_sync(0xffffffffu, SN, o);
        lse_merge(MN, SN, m2, s2);
    }

    if (lane == 0) {
        red[wid * 4 + 0] = MP; red[wid * 4 + 1] = SP;
        red[wid * 4 + 2] = MN; red[wid * 4 + 3] = SN;
    }
    __syncthreads();
    if (t == 0) {
        float mp = red[0], sp = red[1], mn = red[2], sn = red[3];
        #pragma unroll
        for (int w = 1; w < 8; ++w) {
            lse_merge(mp, sp, red[w * 4 + 0], red[w * 4 + 1]);
            lse_merge(mn, sn, red[w * 4 + 2], red[w * 4 + 3]);
        }
        g_pm[bid] = mp; g_ps[bid] = sp;
        g_nm[bid] = mn; g_ns[bid] = sn;
        __threadfence();
        unsigned int prev = atomicAdd(&g_count, 1u);
        *flag = (prev == NJOBS - 1) ? 1u : 0u;
    }
    __syncthreads();

    // Last CTA: final reduction + softplus
    if (*flag) {
        __threadfence();
        float mp = NEG_BIG, sp = 0.0f;
        float mn = NEG_BIG, sn = 0.0f;
        for (int i = t; i < NJOBS; i += 256) {
            lse_merge(mp, sp, g_pm[i], g_ps[i]);
            lse_merge(mn, sn, g_nm[i], g_ns[i]);
        }
        #pragma unroll
        for (int o = 16; o > 0; o >>= 1) {
            float m2 = __shfl_xor_sync(0xffffffffu, mp, o);
            float s2 = __shfl_xor_sync(0xffffffffu, sp, o);
            lse_merge(mp, sp, m2, s2);
            m2 = __shfl_xor_sync(0xffffffffu, mn, o);
            s2 = __shfl_xor_sync(0xffffffffu, sn, o);
            lse_merge(mn, sn, m2, s2);
        }
        __syncthreads();   // red smem reuse
        if (lane == 0) {
            red[wid * 4 + 0] = mp; red[wid * 4 + 1] = sp;
            red[wid * 4 + 2] = mn; red[wid * 4 + 3] = sn;
        }
        __syncthreads();
        if (t == 0) {
            float MPf = red[0], SPf = red[1], MNf = red[2], SNf = red[3];
            #pragma unroll
            for (int w = 1; w < 8; ++w) {
                lse_merge(MPf, SPf, red[w * 4 + 0], red[w * 4 + 1]);
                lse_merge(MNf, SNf, red[w * 4 + 2], red[w * 4 + 3]);
            }
            // convert base-2 LSEs back to natural log
            float x = LN2F * (MPf + log2f(SPf) + MNf + log2f(SNf));
            out[0] = fmaxf(x, 0.0f) + log1pf(__expf(-fabsf(x)));
            g_count = 0;   // reset for next graph replay
        }
    }
}

// ---------------------------------------------------------------------------
extern "C" void kernel_launch(void* const* d_in, const int* in_sizes, int n_in,
                              void* d_out, int out_size) {
    const float* feats = (const float*)d_in[0];
    const int* labels = (const int*)d_in[1];
    float* out = (float*)d_out;

    cudaFuncSetAttribute(sim_lse_kernel,
                         cudaFuncAttributeMaxDynamicSharedMemorySize, SMEM_TOTAL);

    sort_kernel<<<32, 256>>>(labels);
    prep_kernel<<<N_ROWS / 8, 256>>>(feats, labels);
    sim_lse_kernel<<<NJOBS, 256, SMEM_TOTAL>>>(out);
}

// round 16
// speedup vs baseline: 1.3284x; 1.2215x over previous
#include <cuda_runtime.h>
#include <cuda_bf16.h>
#include <math.h>
#include <stdint.h>

// Problem constants
#define N_ROWS 8192
#define DIM 128
#define NCLS 100
#define NTI 64                      // 128-row i-blocks
#define NJOBS 2080                  // pairs of 64-col j-blocks (upper tri)

#define M_MARGIN 0.25f
#define NEG_BIG (-1.0e30f)
#define LN2F 0.6931471805599453f
// gamma' = 256 / ln2 (logits computed in base-2 domain)
#define GP2 369.32993046757465f

// Global bf16 rows (normalized features, label-sorted): [N_ROWS][128]
__device__ __nv_bfloat16 g_h[N_ROWS * DIM];
__device__ int g_lab[N_ROWS];           // sorted labels
__device__ int g_hist[32 * NCLS];       // counts -> then absolute dst offsets
__device__ unsigned char g_rankArr[N_ROWS];

// Per-job LSE partials + completion counter
__device__ float g_pm[NJOBS];
__device__ float g_ps[NJOBS];
__device__ float g_nm[NJOBS];
__device__ float g_ns[NJOBS];
__device__ unsigned int g_count;

// smem rows: 128 bf16 = 256B data + 16B pad = 272 B/row
#define SROW_B 272
#define TI_BYTES (128 * SROW_B)     // 34816
#define TJ_BYTES (64 * SROW_B)      // 17408

#define SM_TI   0
#define SM_TJ0  TI_BYTES
#define SM_TJ1  (TI_BYTES + TJ_BYTES)
#define SM_LR   (TI_BYTES + 2 * TJ_BYTES)      // 128 ints
#define SM_LC0  (SM_LR + 512)                  // 64 ints
#define SM_LC1  (SM_LC0 + 256)                 // 64 ints
#define SM_RED  (SM_LC1 + 256)                 // 32 floats
#define SM_FLAG (SM_RED + 128)                 // 4 bytes
#define SMEM_TOTAL (SM_FLAG + 16)              // ~71 KB

// ---------------------------------------------------------------------------
__device__ __forceinline__ float ex2(float x) {
    float r;
    asm("ex2.approx.f32 %0, %1;" : "=f"(r) : "f"(x));
    return r;
}
// base-2 logsumexp merge
__device__ __forceinline__ void lse_merge(float& m, float& s, float m2, float s2) {
    float mx = fmaxf(m, m2);
    s = s * ex2(m - mx) + s2 * ex2(m2 - mx);
    m = mx;
}

// ---------------------------------------------------------------------------
// Kernel 0a: per-block stable ranks + class histograms (fully parallel).
// 32 blocks x 256 threads.
// ---------------------------------------------------------------------------
__global__ void __launch_bounds__(256)
sort_count_kernel(const int* __restrict__ labels) {
    __shared__ int sh_lab[256];
    const int b = blockIdx.x, t = threadIdx.x;
    const int r = b * 256 + t;

    sh_lab[t] = labels[r];
    __syncthreads();

    // stable in-block rank: count of earlier rows with same label
    int lab = sh_lab[t];
    int rank = 0;
    #pragma unroll 8
    for (int j = 0; j < 256; ++j)
        rank += (j < t && sh_lab[j] == lab) ? 1 : 0;
    g_rankArr[r] = (unsigned char)rank;

    // per-class block counts (threads 0..NCLS-1, broadcast reads)
    if (t < NCLS) {
        int cnt = 0;
        #pragma unroll 8
        for (int j = 0; j < 256; ++j)
            cnt += (sh_lab[j] == t) ? 1 : 0;
        g_hist[b * NCLS + t] = cnt;
    }
}

// ---------------------------------------------------------------------------
// Kernel 0b: convert histograms -> absolute destination offsets.
// 1 block x 128 threads. All chains short; shfl-scan for class prefix.
// ---------------------------------------------------------------------------
__global__ void __launch_bounds__(128)
sort_offsets_kernel() {
    __shared__ int sh[32 * NCLS];        // 12.8 KB
    __shared__ int tot[128];
    __shared__ int wsum[4];
    const int t = threadIdx.x;
    const int lane = t & 31, wd = t >> 5;

    for (int i = t; i < 32 * NCLS; i += 128) sh[i] = g_hist[i];
    __syncthreads();

    // class totals
    int v = 0;
    if (t < NCLS) {
        #pragma unroll
        for (int bb = 0; bb < 32; ++bb) v += sh[bb * NCLS + t];
    }
    tot[t] = v;
    __syncthreads();

    // exclusive prefix over 128 entries (beyond NCLS are 0): shfl scan
    int x = tot[t];
    int inc = x;
    #pragma unroll
    for (int o = 1; o < 32; o <<= 1) {
        int n = __shfl_up_sync(0xffffffffu, inc, o);
        if (lane >= o) inc += n;
    }
    if (lane == 31) wsum[wd] = inc;
    __syncthreads();
    int woff = 0;
    #pragma unroll
    for (int w = 0; w < 4; ++w) woff += (w < wd) ? wsum[w] : 0;
    int start = woff + inc - x;          // exclusive prefix for class t
    __syncthreads();

    // per-(block, class) running offsets
    if (t < NCLS) {
        int run = start;
        #pragma unroll
        for (int bb = 0; bb < 32; ++bb) {
            int c = sh[bb * NCLS + t];
            sh[bb * NCLS + t] = run;
            run += c;
        }
    }
    __syncthreads();
    for (int i = t; i < 32 * NCLS; i += 128) g_hist[i] = sh[i];
}

// ---------------------------------------------------------------------------
// Kernel 1: L2-normalize rows, scatter to label-sorted position.
// Warp per OLD row; dst = g_hist[(old>>8)*NCLS + c] + rank[old].
// ---------------------------------------------------------------------------
__global__ void __launch_bounds__(256)
prep_kernel(const float* __restrict__ feats, const int* __restrict__ labels) {
    int wid = threadIdx.x >> 5;
    int lane = threadIdx.x & 31;
    int old = blockIdx.x * 8 + wid;

    int c = labels[old];                                 // broadcast LDG
    int dst = g_hist[(old >> 8) * NCLS + c] + (int)g_rankArr[old];

    const float4* src = (const float4*)(feats + (size_t)old * DIM);
    float4 v = src[lane];
    float sq = v.x * v.x + v.y * v.y + v.z * v.z + v.w * v.w;
    #pragma unroll
    for (int o = 16; o > 0; o >>= 1) sq += __shfl_xor_sync(0xffffffffu, sq, o);
    float inv = 1.0f / fmaxf(sqrtf(sq), 1e-12f);

    __nv_bfloat162 p0 = __floats2bfloat162_rn(v.x * inv, v.y * inv);
    __nv_bfloat162 p1 = __floats2bfloat162_rn(v.z * inv, v.w * inv);
    uint2 packed = make_uint2(*(uint32_t*)&p0, *(uint32_t*)&p1);
    ((uint2*)(g_h + (size_t)dst * DIM))[lane] = packed;
    if (lane == 0) g_lab[dst] = c;
}

// ---------------------------------------------------------------------------
// mma / ldmatrix / cp.async wrappers
// ---------------------------------------------------------------------------
__device__ __forceinline__ void ldm_x4(uint32_t& r0, uint32_t& r1,
                                       uint32_t& r2, uint32_t& r3,
                                       uint32_t addr) {
    asm volatile("ldmatrix.sync.aligned.m8n8.x4.shared.b16 {%0,%1,%2,%3}, [%4];"
                 : "=r"(r0), "=r"(r1), "=r"(r2), "=r"(r3) : "r"(addr));
}
__device__ __forceinline__ void mma_16816(float* c, const uint32_t* a,
                                          uint32_t b0, uint32_t b1) {
    asm volatile(
        "mma.sync.aligned.m16n8k16.row.col.f32.bf16.bf16.f32 "
        "{%0,%1,%2,%3}, {%4,%5,%6,%7}, {%8,%9}, {%0,%1,%2,%3};"
        : "+f"(c[0]), "+f"(c[1]), "+f"(c[2]), "+f"(c[3])
        : "r"(a[0]), "r"(a[1]), "r"(a[2]), "r"(a[3]), "r"(b0), "r"(b1));
}
__device__ __forceinline__ void cp16(uint32_t dst, const void* src) {
    asm volatile("cp.async.cg.shared.global [%0], [%1], 16;"
                 :: "r"(dst), "l"(src));
}

// pair-jobs per i-block: 64 - ti; offset(ti) = ti*(129-ti)/2
__device__ __forceinline__ int job_offset(int ti) {
    return (ti * (129 - ti)) >> 1;
}

extern __shared__ char smem_dyn[];

// ---------------------------------------------------------------------------
// Mainloop: 128x64 sim, K=128 bf16, 8 warps (4x2). acc[2][4][4] (32 regs).
// ---------------------------------------------------------------------------
__device__ __forceinline__ void mainloop(
    uint32_t baseI, uint32_t baseJ, int wid, int lane, float acc[2][4][4])
{
    const int wr = wid >> 1;
    const int wc = wid & 1;

    #pragma unroll
    for (int i = 0; i < 2; ++i)
        #pragma unroll
        for (int j = 0; j < 4; ++j)
            #pragma unroll
            for (int k = 0; k < 4; ++k) acc[i][j][k] = 0.0f;

    const int lrow16 = lane & 15;
    const int lhalf  = lane >> 4;

    uint32_t aAddr[2], bAddr[2];
    #pragma unroll
    for (int mf = 0; mf < 2; ++mf)
        aAddr[mf] = baseI + (uint32_t)((wr * 32 + mf * 16 + lrow16) * SROW_B + lhalf * 16);
    #pragma unroll
    for (int nb = 0; nb < 2; ++nb)
        bAddr[nb] = baseJ + (uint32_t)((wc * 32 + nb * 16 + lrow16) * SROW_B + lhalf * 16);

    #pragma unroll
    for (int ks = 0; ks < DIM / 16; ++ks) {      // 8 k-steps
        uint32_t kByte = (uint32_t)(ks * 32);
        uint32_t a[2][4], bb[2][4];
        #pragma unroll
        for (int mf = 0; mf < 2; ++mf)
            ldm_x4(a[mf][0], a[mf][1], a[mf][2], a[mf][3], aAddr[mf] + kByte);
        #pragma unroll
        for (int nb = 0; nb < 2; ++nb)
            ldm_x4(bb[nb][0], bb[nb][1], bb[nb][2], bb[nb][3], bAddr[nb] + kByte);
        #pragma unroll
        for (int mf = 0; mf < 2; ++mf) {
            #pragma unroll
            for (int nb = 0; nb < 2; ++nb) {
                mma_16816(acc[mf][2 * nb + 0], a[mf], bb[nb][0], bb[nb][2]);
                mma_16816(acc[mf][2 * nb + 1], a[mf], bb[nb][1], bb[nb][3]);
            }
        }
    }
}

// ---------------------------------------------------------------------------
// Epilogue: sparse-positive two-pass base-2 LSE.
// EQ=false: provably no positive pairs in this subjob (sorted labels).
// ---------------------------------------------------------------------------
template <bool DIAG, bool EQ>
__device__ __forceinline__ void epilogue(
    float acc[2][4][4], const int* lr, const int* lc,
    int ti, int tjh, int wid, int lane,
    float& MP, float& SP, float& MN, float& SN)
{
    const int wr = wid >> 1;
    const int wc = wid & 1;
    const int grp = lane >> 2;
    const int tid4 = lane & 3;

    int lcv[8];
    if (EQ) {
        #pragma unroll
        for (int nf = 0; nf < 4; ++nf)
            #pragma unroll
            for (int cb = 0; cb < 2; ++cb)
                lcv[nf * 2 + cb] = lc[wc * 32 + nf * 8 + tid4 * 2 + cb];
    }

    float mp = NEG_BIG, sp = 0.0f, mn = NEG_BIG;

    // Pass 1: neg logits in-place; eq elements -> pos stream (rare branch)
    #pragma unroll
    for (int mf = 0; mf < 2; ++mf) {
        #pragma unroll
        for (int rh = 0; rh < 2; ++rh) {
            int rloc = wr * 32 + mf * 16 + rh * 8 + grp;
            int li = EQ ? lr[rloc] : 0;
            int gi = ti * 128 + rloc;
            #pragma unroll
            for (int nf = 0; nf < 4; ++nf) {
                #pragma unroll
                for (int cb = 0; cb < 2; ++cb) {
                    float s = acc[mf][nf][rh * 2 + cb];
                    float tn = fmaf(s, GP2, -0.25f * GP2);   // g'(s - 0.25)
                    float un_raw = s + M_MARGIN;
                    float ln = tn * fmaxf(un_raw, 0.0f);
                    if (EQ) {
                        bool eq = (li == lcv[nf * 2 + cb]);
                        if (DIAG) {
                            int cloc = wc * 32 + nf * 8 + tid4 * 2 + cb;
                            bool valid = gi < tjh * 64 + cloc;
                            eq = eq && valid;
                            ln = valid ? ln : -INFINITY;
                        }
                        if (eq) {                            // rare
                            float tp = 0.5f * GP2 - tn;      // g'(0.75 - s)
                            float lp = tp * fmaxf(1.5f - un_raw, 0.0f);
                            float mx = fmaxf(mp, lp);
                            sp = sp * ex2(mp - mx) + ex2(lp - mx);
                            mp = mx;
                            ln = -INFINITY;                  // exclude from neg
                        }
                    }
                    acc[mf][nf][rh * 2 + cb] = ln;
                    mn = fmaxf(mn, ln);
                }
            }
        }
    }

    // Pass 2: unconditional neg accumulate
    float sn = 0.0f;
    #pragma unroll
    for (int mf = 0; mf < 2; ++mf)
        #pragma unroll
        for (int rh = 0; rh < 2; ++rh)
            #pragma unroll
            for (int nf = 0; nf < 4; ++nf)
                #pragma unroll
                for (int cb = 0; cb < 2; ++cb)
                    sn += ex2(acc[mf][nf][rh * 2 + cb] - mn);

    if (EQ) lse_merge(MP, SP, mp, sp);
    lse_merge(MN, SN, mn, sn);
}

// ---------------------------------------------------------------------------
// Kernel 2: pair-job per CTA + fused last-block final reduction.
// ---------------------------------------------------------------------------
__global__ void __launch_bounds__(256, 3)
sim_lse_kernel(float* __restrict__ out) {
    const int bid = blockIdx.x;
    const int t = threadIdx.x;
    const int wid = t >> 5;
    const int lane = t & 31;

    // invert pair-job index: offset(ti) = ti*(129-ti)/2
    int L = bid;
    float disc = 129.0f * 129.0f - 8.0f * (float)L;
    int ti = (int)((129.0f - sqrtf(disc)) * 0.5f);
    if (ti < 0) ti = 0;
    if (ti > NTI - 1) ti = NTI - 1;
    while (ti + 1 <= NTI - 1 && job_offset(ti + 1) <= L) ++ti;
    while (job_offset(ti) > L) --ti;
    const int p = L - job_offset(ti);
    const int tjh0 = 2 * ti + 2 * p;
    const int tjh1 = tjh0 + 1;
    const bool diag = (p == 0);

    char* smem = smem_dyn;
    uint32_t baseI  = (uint32_t)__cvta_generic_to_shared(smem + SM_TI);
    uint32_t baseJ0 = (uint32_t)__cvta_generic_to_shared(smem + SM_TJ0);
    uint32_t baseJ1 = (uint32_t)__cvta_generic_to_shared(smem + SM_TJ1);
    int* lr = (int*)(smem + SM_LR);
    int* lc0 = (int*)(smem + SM_LC0);
    int* lc1 = (int*)(smem + SM_LC1);
    float* red = (float*)(smem + SM_RED);
    unsigned int* flag = (unsigned int*)(smem + SM_FLAG);

    // Load I + J0 + J1 upfront (one async group)
    {
        const char* srcI  = (const char*)(g_h + (size_t)ti * 128 * DIM);
        const char* srcJ0 = (const char*)(g_h + (size_t)tjh0 * 64 * DIM);
        const char* srcJ1 = (const char*)(g_h + (size_t)tjh1 * 64 * DIM);
        #pragma unroll
        for (int it = 0; it < 8; ++it) {
            int idx = t + it * 256;
            int r = idx >> 4, c = idx & 15;
            cp16(baseI + r * SROW_B + c * 16, srcI + idx * 16);
        }
        #pragma unroll
        for (int it = 0; it < 4; ++it) {
            int idx = t + it * 256;
            int r = idx >> 4, c = idx & 15;
            cp16(baseJ0 + r * SROW_B + c * 16, srcJ0 + idx * 16);
        }
        #pragma unroll
        for (int it = 0; it < 4; ++it) {
            int idx = t + it * 256;
            int r = idx >> 4, c = idx & 15;
            cp16(baseJ1 + r * SROW_B + c * 16, srcJ1 + idx * 16);
        }
        asm volatile("cp.async.commit_group;");
    }
    if (t < 128) lr[t] = g_lab[ti * 128 + t];
    if (t < 64)  lc0[t] = g_lab[tjh0 * 64 + t];
    if (t >= 64 && t < 128) lc1[t - 64] = g_lab[tjh1 * 64 + (t - 64)];
    asm volatile("cp.async.wait_group 0;");
    __syncthreads();

    // sorted labels: subjob has positives iff label ranges intersect
    const bool eq0 = diag || (lr[127] == lc0[0]);
    const bool eq1 = diag || (lr[127] == lc1[0]);

    float MP = NEG_BIG, SP = 0.0f, MN = NEG_BIG, SN = 0.0f;
    float acc[2][4][4];

    mainloop(baseI, baseJ0, wid, lane, acc);
    if (diag)     epilogue<true,  true >(acc, lr, lc0, ti, tjh0, wid, lane, MP, SP, MN, SN);
    else if (eq0) epilogue<false, true >(acc, lr, lc0, ti, tjh0, wid, lane, MP, SP, MN, SN);
    else          epilogue<false, false>(acc, lr, lc0, ti, tjh0, wid, lane, MP, SP, MN, SN);

    mainloop(baseI, baseJ1, wid, lane, acc);
    if (diag)     epilogue<true,  true >(acc, lr, lc1, ti, tjh1, wid, lane, MP, SP, MN, SN);
    else if (eq1) epilogue<false, true >(acc, lr, lc1, ti, tjh1, wid, lane, MP, SP, MN, SN);
    else          epilogue<false, false>(acc, lr, lc1, ti, tjh1, wid, lane, MP, SP, MN, SN);

    // Warp reduction
    #pragma unroll
    for (int o = 16; o > 0; o >>= 1) {
        float m2 = __shfl_xor_sync(0xffffffffu, MP, o);
        float s2 = __shfl_xor_sync(0xffffffffu, SP, o);
        lse_merge(MP, SP, m2, s2);
        m2 = __shfl_xor_sync(0xffffffffu, MN, o);
        s2 = __shfl_xor_sync(0xffffffffu, SN, o);
        lse_merge(MN, SN, m2, s2);
    }

    if (lane == 0) {
        red[wid * 4 + 0] = MP; red[wid * 4 + 1] = SP;
        red[wid * 4 + 2] = MN; red[wid * 4 + 3] = SN;
    }
    __syncthreads();
    if (t == 0) {
        float mp = red[0], sp = red[1], mn = red[2], sn = red[3];
        #pragma unroll
        for (int w = 1; w < 8; ++w) {
            lse_merge(mp, sp, red[w * 4 + 0], red[w * 4 + 1]);
            lse_merge(mn, sn, red[w * 4 + 2], red[w * 4 + 3]);
        }
        g_pm[bid] = mp; g_ps[bid] = sp;
        g_nm[bid] = mn; g_ns[bid] = sn;
        __threadfence();
        unsigned int prev = atomicAdd(&g_count, 1u);
        *flag = (prev == NJOBS - 1) ? 1u : 0u;
    }
    __syncthreads();

    // Last CTA: final reduction + softplus
    if (*flag) {
        __threadfence();
        float mp = NEG_BIG, sp = 0.0f;
        float mn = NEG_BIG, sn = 0.0f;
        for (int i = t; i < NJOBS; i += 256) {
            lse_merge(mp, sp, g_pm[i], g_ps[i]);
            lse_merge(mn, sn, g_nm[i], g_ns[i]);
        }
        #pragma unroll
        for (int o = 16; o > 0; o >>= 1) {
            float m2 = __shfl_xor_sync(0xffffffffu, mp, o);
            float s2 = __shfl_xor_sync(0xffffffffu, sp, o);
            lse_merge(mp, sp, m2, s2);
            m2 = __shfl_xor_sync(0xffffffffu, mn, o);
            s2 = __shfl_xor_sync(0xffffffffu, sn, o);
            lse_merge(mn, sn, m2, s2);
        }
        __syncthreads();   // red smem reuse
        if (lane == 0) {
            red[wid * 4 + 0] = mp; red[wid * 4 + 1] = sp;
            red[wid * 4 + 2] = mn; red[wid * 4 + 3] = sn;
        }
        __syncthreads();
        if (t == 0) {
            float MPf = red[0], SPf = red[1], MNf = red[2], SNf = red[3];
            #pragma unroll
            for (int w = 1; w < 8; ++w) {
                lse_merge(MPf, SPf, red[w * 4 + 0], red[w * 4 + 1]);
                lse_merge(MNf, SNf, red[w * 4 + 2], red[w * 4 + 3]);
            }
            // convert base-2 LSEs back to natural log
            float x = LN2F * (MPf + log2f(SPf) + MNf + log2f(SNf));
            out[0] = fmaxf(x, 0.0f) + log1pf(__expf(-fabsf(x)));
            g_count = 0;   // reset for next graph replay
        }
    }
}

// ---------------------------------------------------------------------------
extern "C" void kernel_launch(void* const* d_in, const int* in_sizes, int n_in,
                              void* d_out, int out_size) {
    const float* feats = (const float*)d_in[0];
    const int* labels = (const int*)d_in[1];
    float* out = (float*)d_out;

    cudaFuncSetAttribute(sim_lse_kernel,
                         cudaFuncAttributeMaxDynamicSharedMemorySize, SMEM_TOTAL);

    sort_count_kernel<<<32, 256>>>(labels);
    sort_offsets_kernel<<<1, 128>>>();
    prep_kernel<<<N_ROWS / 8, 256>>>(feats, labels);
    sim_lse_kernel<<<NJOBS, 256, SMEM_TOTAL>>>(out);
}

// round 17
// speedup vs baseline: 1.3380x; 1.0072x over previous
#include <cuda_runtime.h>
#include <cuda_bf16.h>
#include <math.h>
#include <stdint.h>

// Problem constants
#define N_ROWS 8192
#define DIM 128
#define NCLS 100
#define NTI 64                      // 128-row i-blocks
#define NJOBS 2080                  // pairs of 64-col j-blocks (upper tri)

#define M_MARGIN 0.25f
#define NEG_BIG (-1.0e30f)
#define LN2F 0.6931471805599453f
// gamma' = 256 / ln2 (logits computed in base-2 domain)
#define GP2 369.32993046757465f

// Global bf16 rows (normalized features, label-sorted): [N_ROWS][128]
__device__ __nv_bfloat16 g_h[N_ROWS * DIM];
__device__ int g_lab[N_ROWS];           // sorted labels
__device__ int g_hist[32 * NCLS];       // counts -> then absolute dst offsets
__device__ unsigned char g_rankArr[N_ROWS];

// Per-job LSE partials + completion counter
__device__ float g_pm[NJOBS];
__device__ float g_ps[NJOBS];
__device__ float g_nm[NJOBS];
__device__ float g_ns[NJOBS];
__device__ unsigned int g_count;

// smem rows: 128 bf16 = 256B data + 16B pad = 272 B/row
#define SROW_B 272
#define TI_BYTES (128 * SROW_B)     // 34816
#define TJ_BYTES (64 * SROW_B)      // 17408

#define SM_TI   0
#define SM_TJ0  TI_BYTES
#define SM_TJ1  (TI_BYTES + TJ_BYTES)
#define SM_LR   (TI_BYTES + 2 * TJ_BYTES)      // 128 ints
#define SM_LC0  (SM_LR + 512)                  // 64 ints
#define SM_LC1  (SM_LC0 + 256)                 // 64 ints
#define SM_RED  (SM_LC1 + 256)                 // 32 floats
#define SM_FLAG (SM_RED + 128)                 // 4 bytes
#define SMEM_TOTAL (SM_FLAG + 16)              // ~71 KB (still < 228/3... 4 CTAs need <57KB? no - smem is the other limit)

// NOTE: 4 CTAs/SM would need smem <= 57KB; we have ~71KB -> smem caps at 3 CTAs.
// So shrink smem: drop the J1 buffer and double-buffer J in TJ0/TJ1 halves is
// already what we have. Instead: reduce to I + J0 + J1 but trim padding is
// impossible... -> use 4-CTA REGISTER target anyway: occupancy limited by
// min(regs, smem). To actually reach 4 CTAs, cut smem below 57,344 B by
// dropping the separate J1 buffer and prefetching J1 into J0's buffer after
// subjob-0 (costs one mid-kernel sync, which epilogue-0 overlaps).
#undef SM_TJ1
#undef SM_LR
#undef SM_LC0
#undef SM_LC1
#undef SM_RED
#undef SM_FLAG
#undef SMEM_TOTAL
#define SM_LR   (TI_BYTES + TJ_BYTES)          // 128 ints
#define SM_LC0  (SM_LR + 512)                  // 64 ints
#define SM_LC1  (SM_LC0 + 256)                 // 64 ints
#define SM_RED  (SM_LC1 + 256)                 // 32 floats
#define SM_FLAG (SM_RED + 128)                 // 4 bytes
#define SMEM_TOTAL (SM_FLAG + 16)              // ~53.5 KB -> 4 CTAs/SM

// ---------------------------------------------------------------------------
__device__ __forceinline__ float ex2(float x) {
    float r;
    asm("ex2.approx.f32 %0, %1;" : "=f"(r) : "f"(x));
    return r;
}
// base-2 logsumexp merge
__device__ __forceinline__ void lse_merge(float& m, float& s, float m2, float s2) {
    float mx = fmaxf(m, m2);
    s = s * ex2(m - mx) + s2 * ex2(m2 - mx);
    m = mx;
}

// ---------------------------------------------------------------------------
// Kernel 0a: per-block stable ranks + class histograms (fully parallel).
// ---------------------------------------------------------------------------
__global__ void __launch_bounds__(256)
sort_count_kernel(const int* __restrict__ labels) {
    __shared__ int sh_lab[256];
    const int b = blockIdx.x, t = threadIdx.x;
    const int r = b * 256 + t;

    sh_lab[t] = labels[r];
    __syncthreads();

    int lab = sh_lab[t];
    int rank = 0;
    #pragma unroll 8
    for (int j = 0; j < 256; ++j)
        rank += (j < t && sh_lab[j] == lab) ? 1 : 0;
    g_rankArr[r] = (unsigned char)rank;

    if (t < NCLS) {
        int cnt = 0;
        #pragma unroll 8
        for (int j = 0; j < 256; ++j)
            cnt += (sh_lab[j] == t) ? 1 : 0;
        g_hist[b * NCLS + t] = cnt;
    }
}

// ---------------------------------------------------------------------------
// Kernel 0b: histograms -> absolute destination offsets.
// ---------------------------------------------------------------------------
__global__ void __launch_bounds__(128)
sort_offsets_kernel() {
    __shared__ int sh[32 * NCLS];
    __shared__ int tot[128];
    __shared__ int wsum[4];
    const int t = threadIdx.x;
    const int lane = t & 31, wd = t >> 5;

    for (int i = t; i < 32 * NCLS; i += 128) sh[i] = g_hist[i];
    __syncthreads();

    int v = 0;
    if (t < NCLS) {
        #pragma unroll
        for (int bb = 0; bb < 32; ++bb) v += sh[bb * NCLS + t];
    }
    tot[t] = v;
    __syncthreads();

    int x = tot[t];
    int inc = x;
    #pragma unroll
    for (int o = 1; o < 32; o <<= 1) {
        int n = __shfl_up_sync(0xffffffffu, inc, o);
        if (lane >= o) inc += n;
    }
    if (lane == 31) wsum[wd] = inc;
    __syncthreads();
    int woff = 0;
    #pragma unroll
    for (int w = 0; w < 4; ++w) woff += (w < wd) ? wsum[w] : 0;
    int start = woff + inc - x;
    __syncthreads();

    if (t < NCLS) {
        int run = start;
        #pragma unroll
        for (int bb = 0; bb < 32; ++bb) {
            int c = sh[bb * NCLS + t];
            sh[bb * NCLS + t] = run;
            run += c;
        }
    }
    __syncthreads();
    for (int i = t; i < 32 * NCLS; i += 128) g_hist[i] = sh[i];
}

// ---------------------------------------------------------------------------
// Kernel 1: L2-normalize rows, scatter to label-sorted position.
// ---------------------------------------------------------------------------
__global__ void __launch_bounds__(256)
prep_kernel(const float* __restrict__ feats, const int* __restrict__ labels) {
    int wid = threadIdx.x >> 5;
    int lane = threadIdx.x & 31;
    int old = blockIdx.x * 8 + wid;

    int c = labels[old];
    int dst = g_hist[(old >> 8) * NCLS + c] + (int)g_rankArr[old];

    const float4* src = (const float4*)(feats + (size_t)old * DIM);
    float4 v = src[lane];
    float sq = v.x * v.x + v.y * v.y + v.z * v.z + v.w * v.w;
    #pragma unroll
    for (int o = 16; o > 0; o >>= 1) sq += __shfl_xor_sync(0xffffffffu, sq, o);
    float inv = 1.0f / fmaxf(sqrtf(sq), 1e-12f);

    __nv_bfloat162 p0 = __floats2bfloat162_rn(v.x * inv, v.y * inv);
    __nv_bfloat162 p1 = __floats2bfloat162_rn(v.z * inv, v.w * inv);
    uint2 packed = make_uint2(*(uint32_t*)&p0, *(uint32_t*)&p1);
    ((uint2*)(g_h + (size_t)dst * DIM))[lane] = packed;
    if (lane == 0) g_lab[dst] = c;
}

// ---------------------------------------------------------------------------
// mma / ldmatrix / cp.async wrappers
// ---------------------------------------------------------------------------
__device__ __forceinline__ void ldm_x4(uint32_t& r0, uint32_t& r1,
                                       uint32_t& r2, uint32_t& r3,
                                       uint32_t addr) {
    asm volatile("ldmatrix.sync.aligned.m8n8.x4.shared.b16 {%0,%1,%2,%3}, [%4];"
                 : "=r"(r0), "=r"(r1), "=r"(r2), "=r"(r3) : "r"(addr));
}
__device__ __forceinline__ void mma_16816(float* c, const uint32_t* a,
                                          uint32_t b0, uint32_t b1) {
    asm volatile(
        "mma.sync.aligned.m16n8k16.row.col.f32.bf16.bf16.f32 "
        "{%0,%1,%2,%3}, {%4,%5,%6,%7}, {%8,%9}, {%0,%1,%2,%3};"
        : "+f"(c[0]), "+f"(c[1]), "+f"(c[2]), "+f"(c[3])
        : "r"(a[0]), "r"(a[1]), "r"(a[2]), "r"(a[3]), "r"(b0), "r"(b1));
}
__device__ __forceinline__ void cp16(uint32_t dst, const void* src) {
    asm volatile("cp.async.cg.shared.global [%0], [%1], 16;"
                 :: "r"(dst), "l"(src));
}

__device__ __forceinline__ int job_offset(int ti) {
    return (ti * (129 - ti)) >> 1;
}

extern __shared__ char smem_dyn[];

// ---------------------------------------------------------------------------
// Mainloop: 128x64 sim, K=128 bf16, 8 warps (4x2). acc[2][4][4] (32 regs).
// ---------------------------------------------------------------------------
__device__ __forceinline__ void mainloop(
    uint32_t baseI, uint32_t baseJ, int wid, int lane, float acc[2][4][4])
{
    const int wr = wid >> 1;
    const int wc = wid & 1;

    #pragma unroll
    for (int i = 0; i < 2; ++i)
        #pragma unroll
        for (int j = 0; j < 4; ++j)
            #pragma unroll
            for (int k = 0; k < 4; ++k) acc[i][j][k] = 0.0f;

    const int lrow16 = lane & 15;
    const int lhalf  = lane >> 4;

    uint32_t aAddr[2], bAddr[2];
    #pragma unroll
    for (int mf = 0; mf < 2; ++mf)
        aAddr[mf] = baseI + (uint32_t)((wr * 32 + mf * 16 + lrow16) * SROW_B + lhalf * 16);
    #pragma unroll
    for (int nb = 0; nb < 2; ++nb)
        bAddr[nb] = baseJ + (uint32_t)((wc * 32 + nb * 16 + lrow16) * SROW_B + lhalf * 16);

    #pragma unroll
    for (int ks = 0; ks < DIM / 16; ++ks) {      // 8 k-steps
        uint32_t kByte = (uint32_t)(ks * 32);
        uint32_t a[2][4], bb[2][4];
        #pragma unroll
        for (int mf = 0; mf < 2; ++mf)
            ldm_x4(a[mf][0], a[mf][1], a[mf][2], a[mf][3], aAddr[mf] + kByte);
        #pragma unroll
        for (int nb = 0; nb < 2; ++nb)
            ldm_x4(bb[nb][0], bb[nb][1], bb[nb][2], bb[nb][3], bAddr[nb] + kByte);
        #pragma unroll
        for (int mf = 0; mf < 2; ++mf) {
            #pragma unroll
            for (int nb = 0; nb < 2; ++nb) {
                mma_16816(acc[mf][2 * nb + 0], a[mf], bb[nb][0], bb[nb][2]);
                mma_16816(acc[mf][2 * nb + 1], a[mf], bb[nb][1], bb[nb][3]);
            }
        }
    }
}

// ---------------------------------------------------------------------------
// Epilogue: sparse-positive two-pass base-2 LSE.
// ---------------------------------------------------------------------------
template <bool DIAG, bool EQ>
__device__ __forceinline__ void epilogue(
    float acc[2][4][4], const int* lr, const int* lc,
    int ti, int tjh, int wid, int lane,
    float& MP, float& SP, float& MN, float& SN)
{
    const int wr = wid >> 1;
    const int wc = wid & 1;
    const int grp = lane >> 2;
    const int tid4 = lane & 3;

    float mp = NEG_BIG, sp = 0.0f, mn = NEG_BIG;

    #pragma unroll
    for (int mf = 0; mf < 2; ++mf) {
        #pragma unroll
        for (int rh = 0; rh < 2; ++rh) {
            int rloc = wr * 32 + mf * 16 + rh * 8 + grp;
            int li = EQ ? lr[rloc] : 0;
            int gi = ti * 128 + rloc;
            #pragma unroll
            for (int nf = 0; nf < 4; ++nf) {
                #pragma unroll
                for (int cb = 0; cb < 2; ++cb) {
                    float s = acc[mf][nf][rh * 2 + cb];
                    float tn = fmaf(s, GP2, -0.25f * GP2);   // g'(s - 0.25)
                    float un_raw = s + M_MARGIN;
                    float ln = tn * fmaxf(un_raw, 0.0f);
                    if (EQ) {
                        int cloc = wc * 32 + nf * 8 + tid4 * 2 + cb;
                        bool eq = (li == lc[cloc]);          // smem load (LDS)
                        if (DIAG) {
                            bool valid = gi < tjh * 64 + cloc;
                            eq = eq && valid;
                            ln = valid ? ln : -INFINITY;
                        }
                        if (eq) {                            // rare
                            float tp = 0.5f * GP2 - tn;      // g'(0.75 - s)
                            float lp = tp * fmaxf(1.5f - un_raw, 0.0f);
                            float mx = fmaxf(mp, lp);
                            sp = sp * ex2(mp - mx) + ex2(lp - mx);
                            mp = mx;
                            ln = -INFINITY;                  // exclude from neg
                        }
                    }
                    acc[mf][nf][rh * 2 + cb] = ln;
                    mn = fmaxf(mn, ln);
                }
            }
        }
    }

    // Pass 2: unconditional neg accumulate
    float sn = 0.0f;
    #pragma unroll
    for (int mf = 0; mf < 2; ++mf)
        #pragma unroll
        for (int rh = 0; rh < 2; ++rh)
            #pragma unroll
            for (int nf = 0; nf < 4; ++nf)
                #pragma unroll
                for (int cb = 0; cb < 2; ++cb)
                    sn += ex2(acc[mf][nf][rh * 2 + cb] - mn);

    if (EQ) lse_merge(MP, SP, mp, sp);
    lse_merge(MN, SN, mn, sn);
}

// ---------------------------------------------------------------------------
// Kernel 2: pair-job per CTA, 4 CTAs/SM (64-reg cap, 53.5KB smem).
// J1 prefetched into the single J buffer after subjob 0's mainloop,
// overlapped with epilogue 0.
// ---------------------------------------------------------------------------
__global__ void __launch_bounds__(256, 4)
sim_lse_kernel(float* __restrict__ out) {
    const int bid = blockIdx.x;
    const int t = threadIdx.x;
    const int wid = t >> 5;
    const int lane = t & 31;

    // invert pair-job index: offset(ti) = ti*(129-ti)/2
    int L = bid;
    float disc = 129.0f * 129.0f - 8.0f * (float)L;
    int ti = (int)((129.0f - sqrtf(disc)) * 0.5f);
    if (ti < 0) ti = 0;
    if (ti > NTI - 1) ti = NTI - 1;
    while (ti + 1 <= NTI - 1 && job_offset(ti + 1) <= L) ++ti;
    while (job_offset(ti) > L) --ti;
    const int p = L - job_offset(ti);
    const int tjh0 = 2 * ti + 2 * p;
    const int tjh1 = tjh0 + 1;
    const bool diag = (p == 0);

    char* smem = smem_dyn;
    uint32_t baseI = (uint32_t)__cvta_generic_to_shared(smem + SM_TI);
    uint32_t baseJ = (uint32_t)__cvta_generic_to_shared(smem + SM_TJ0);
    int* lr = (int*)(smem + SM_LR);
    int* lc0 = (int*)(smem + SM_LC0);
    int* lc1 = (int*)(smem + SM_LC1);

    // Load I + J0 (one async group)
    {
        const char* srcI  = (const char*)(g_h + (size_t)ti * 128 * DIM);
        const char* srcJ0 = (const char*)(g_h + (size_t)tjh0 * 64 * DIM);
        #pragma unroll
        for (int it = 0; it < 8; ++it) {
            int idx = t + it * 256;
            int r = idx >> 4, c = idx & 15;
            cp16(baseI + r * SROW_B + c * 16, srcI + idx * 16);
        }
        #pragma unroll
        for (int it = 0; it < 4; ++it) {
            int idx = t + it * 256;
            int r = idx >> 4, c = idx & 15;
            cp16(baseJ + r * SROW_B + c * 16, srcJ0 + idx * 16);
        }
        asm volatile("cp.async.commit_group;");
    }
    if (t < 128) lr[t] = g_lab[ti * 128 + t];
    if (t < 64)  lc0[t] = g_lab[tjh0 * 64 + t];
    if (t >= 64 && t < 128) lc1[t - 64] = g_lab[tjh1 * 64 + (t - 64)];
    asm volatile("cp.async.wait_group 0;");
    __syncthreads();

    const bool eq0 = diag || (lr[127] == lc0[0]);
    const bool eq1 = diag || (lr[127] == lc1[0]);

    float MP = NEG_BIG, SP = 0.0f, MN = NEG_BIG, SN = 0.0f;
    float acc[2][4][4];

    // sub-job 0 mainloop
    mainloop(baseI, baseJ, wid, lane, acc);

    // all warps done reading J buffer; prefetch J1, overlap with epilogue 0
    __syncthreads();
    {
        const char* srcJ1 = (const char*)(g_h + (size_t)tjh1 * 64 * DIM);
        #pragma unroll
        for (int it = 0; it < 4; ++it) {
            int idx = t + it * 256;
            int r = idx >> 4, c = idx & 15;
            cp16(baseJ + r * SROW_B + c * 16, srcJ1 + idx * 16);
        }
        asm volatile("cp.async.commit_group;");
    }

    if (diag)     epilogue<true,  true >(acc, lr, lc0, ti, tjh0, wid, lane, MP, SP, MN, SN);
    else if (eq0) epilogue<false, true >(acc, lr, lc0, ti, tjh0, wid, lane, MP, SP, MN, SN);
    else          epilogue<false, false>(acc, lr, lc0, ti, tjh0, wid, lane, MP, SP, MN, SN);

    asm volatile("cp.async.wait_group 0;");
    __syncthreads();

    // sub-job 1
    mainloop(baseI, baseJ, wid, lane, acc);
    if (diag)     epilogue<true,  true >(acc, lr, lc1, ti, tjh1, wid, lane, MP, SP, MN, SN);
    else if (eq1) epilogue<false, true >(acc, lr, lc1, ti, tjh1, wid, lane, MP, SP, MN, SN);
    else          epilogue<false, false>(acc, lr, lc1, ti, tjh1, wid, lane, MP, SP, MN, SN);

    // Warp reduction
    #pragma unroll
    for (int o = 16; o > 0; o >>= 1) {
        float m2 = __shfl_xor_sync(0xffffffffu, MP, o);
        float s2 = __shfl_xor_sync(0xffffffffu, SP, o);
        lse_merge(MP, SP, m2, s2);
        m2 = __shfl_xor_sync(0xffffffffu, MN, o);
        s2 = __shfl_xor_sync(0xffffffffu, SN, o);
        lse_merge(MN, SN, m2, s2);
    }

    float* red = (float*)(smem + SM_RED);
    unsigned int* flag = (unsigned int*)(smem + SM_FLAG);
    if (lane == 0) {
        red[wid * 4 + 0] = MP; red[wid * 4 + 1] = SP;
        red[wid * 4 + 2] = MN; red[wid * 4 + 3] = SN;
    }
    __syncthreads();
    if (t == 0) {
        float mp = red[0], sp = red[1], mn = red[2], sn = red[3];
        #pragma unroll
        for (int w = 1; w < 8; ++w) {
            lse_merge(mp, sp, red[w * 4 + 0], red[w * 4 + 1]);
            lse_merge(mn, sn, red[w * 4 + 2], red[w * 4 + 3]);
        }
        g_pm[bid] = mp; g_ps[bid] = sp;
        g_nm[bid] = mn; g_ns[bid] = sn;
        __threadfence();
        unsigned int prev = atomicAdd(&g_count, 1u);
        *flag = (prev == NJOBS - 1) ? 1u : 0u;
    }
    __syncthreads();

    // Last CTA: final reduction + softplus
    if (*flag) {
        __threadfence();
        float mp = NEG_BIG, sp = 0.0f;
        float mn = NEG_BIG, sn = 0.0f;
        for (int i = t; i < NJOBS; i += 256) {
            lse_merge(mp, sp, g_pm[i], g_ps[i]);
            lse_merge(mn, sn, g_nm[i], g_ns[i]);
        }
        #pragma unroll
        for (int o = 16; o > 0; o >>= 1) {
            float m2 = __shfl_xor_sync(0xffffffffu, mp, o);
            float s2 = __shfl_xor_sync(0xffffffffu, sp, o);
            lse_merge(mp, sp, m2, s2);
            m2 = __shfl_xor_sync(0xffffffffu, mn, o);
            s2 = __shfl_xor_sync(0xffffffffu, sn, o);
            lse_merge(mn, sn, m2, s2);
        }
        __syncthreads();
        if (lane == 0) {
            red[wid * 4 + 0] = mp; red[wid * 4 + 1] = sp;
            red[wid * 4 + 2] = mn; red[wid * 4 + 3] = sn;
        }
        __syncthreads();
        if (t == 0) {
            float MPf = red[0], SPf = red[1], MNf = red[2], SNf = red[3];
            #pragma unroll
            for (int w = 1; w < 8; ++w) {
                lse_merge(MPf, SPf, red[w * 4 + 0], red[w * 4 + 1]);
                lse_merge(MNf, SNf, red[w * 4 + 2], red[w * 4 + 3]);
            }
            float x = LN2F * (MPf + log2f(SPf) + MNf + log2f(SNf));
            out[0] = fmaxf(x, 0.0f) + log1pf(__expf(-fabsf(x)));
            g_count = 0;   // reset for next graph replay
        }
    }
}

// ---------------------------------------------------------------------------
extern "C" void kernel_launch(void* const* d_in, const int* in_sizes, int n_in,
                              void* d_out, int out_size) {
    const float* feats = (const float*)d_in[0];
    const int* labels = (const int*)d_in[1];
    float* out = (float*)d_out;

    cudaFuncSetAttribute(sim_lse_kernel,
                         cudaFuncAttributeMaxDynamicSharedMemorySize, SMEM_TOTAL);

    sort_count_kernel<<<32, 256>>>(labels);
    sort_offsets_kernel<<<1, 128>>>();
    prep_kernel<<<N_ROWS / 8, 256>>>(feats, labels);
    sim_lse_kernel<<<NJOBS, 256, SMEM_TOTAL>>>(out);
}